// round 4
// baseline (speedup 1.0000x reference)
#include <cuda_runtime.h>

typedef unsigned long long u64;

#define NSTEP 256   // C2
#define NTH   256   // threads per block; thread t owns complex elements 4t..4t+3
#define G     4     // f32x2 row-groups (2 batch rows each) -> 8 rows per block

// Pre-packed broadcast coefficients: [step][chunk 0..15][thread], each chunk is
// a float4 = two duplicated-pair u64s ready for f32x2 ops (incl. pre-negated).
// 256*16*256*16B = 16.8 MB (fits L2).
__device__ float4 gC[NSTEP * 16 * NTH];

__device__ __forceinline__ u64 pk(float lo, float hi) {
    u64 r; asm("mov.b64 %0, {%1, %2};" : "=l"(r) : "f"(lo), "f"(hi)); return r;
}
__device__ __forceinline__ void upk(u64 v, float& lo, float& hi) {
    asm("mov.b64 {%0, %1}, %2;" : "=f"(lo), "=f"(hi) : "l"(v));
}
__device__ __forceinline__ u64 mul2(u64 a, u64 b) {
    u64 r; asm("mul.rn.f32x2 %0, %1, %2;" : "=l"(r) : "l"(a), "l"(b)); return r;
}
__device__ __forceinline__ u64 fma2(u64 a, u64 b, u64 c) {
    u64 r; asm("fma.rn.f32x2 %0, %1, %2, %3;" : "=l"(r) : "l"(a), "l"(b), "l"(c)); return r;
}

// phi/theta arrays: (H2=512, C2=256) row-major -> [p*256 + c]
__global__ void coeff_kernel(const float* __restrict__ phi0, const float* __restrict__ th0,
                             const float* __restrict__ phi1, const float* __restrict__ th1) {
    int idx = blockIdx.x * blockDim.x + threadIdx.x;
    if (idx >= NSTEP * 512) return;
    int p = idx & 511;     // pair index
    int c = idx >> 9;      // step
    int t = p >> 1;        // owning eunn-thread
    int base = c * 16 * NTH;

    float sp, cp, st, ct;
    sincosf(phi0[p * NSTEP + c], &sp, &cp);
    sincosf(th0[p * NSTEP + c], &st, &ct);
    {
        float dr = cp * ct, di = sp * ct, orr = -cp * st, oi = -sp * st;
        int cb = (p & 1) ? 4 : 0;   // A pair0 -> chunks 0..3, A pair1 -> 4..7
        gC[base + (cb + 0) * NTH + t] = make_float4(dr, dr, di, di);
        gC[base + (cb + 1) * NTH + t] = make_float4(-di, -di, orr, orr);
        gC[base + (cb + 2) * NTH + t] = make_float4(oi, oi, -oi, -oi);
        gC[base + (cb + 3) * NTH + t] = make_float4(ct, ct, st, st);
    }

    sincosf(phi1[p * NSTEP + c], &sp, &cp);
    sincosf(th1[p * NSTEP + c], &st, &ct);
    {
        float dr = cp * ct, di = sp * ct, orr = -cp * st, oi = -sp * st;
        if ((p & 1) == 0) {
            // B local pair (e1,e2) of thread t -> chunks 8..11
            gC[base + 8 * NTH + t]  = make_float4(dr, dr, di, di);
            gC[base + 9 * NTH + t]  = make_float4(-di, -di, orr, orr);
            gC[base + 10 * NTH + t] = make_float4(oi, oi, -oi, -oi);
            gC[base + 11 * NTH + t] = make_float4(ct, ct, st, st);
        } else {
            // B boundary pair (e3, nb_e0) of thread t -> chunks 12..14
            gC[base + 12 * NTH + t] = make_float4(dr, dr, di, di);
            gC[base + 13 * NTH + t] = make_float4(-di, -di, orr, orr);
            gC[base + 14 * NTH + t] = make_float4(oi, oi, -oi, -oi);
            // (ct,st) consumed as "previous pair" by thread t+1 (mod 256) -> its chunk 15
            int ts = (t + 1) & (NTH - 1);
            gC[base + 15 * NTH + ts] = make_float4(ct, ct, st, st);
        }
    }
}

__global__ void __launch_bounds__(NTH, 2)
eunn_kernel(const float4* __restrict__ xin, float4* __restrict__ xout) {
    const int t    = threadIdx.x;
    const int lane = t & 31;
    const int w    = t >> 5;               // 8 warps
    const int row0 = blockIdx.x * (2 * G); // 8 batch rows per block
    const ulonglong2* __restrict__ C = (const ulonglong2*)gC;

    u64 e0r[G], e0i[G], e1r[G], e1i[G], e2r[G], e2i[G], e3r[G], e3i[G];
#pragma unroll
    for (int g = 0; g < G; g++) {
        size_t r0 = (size_t)(row0 + 2 * g) * 512;
        size_t r1 = r0 + 512;
        float4 a0 = xin[r0 + 2 * t], a1 = xin[r0 + 2 * t + 1];
        float4 b0 = xin[r1 + 2 * t], b1 = xin[r1 + 2 * t + 1];
        e0r[g] = pk(a0.x, b0.x); e0i[g] = pk(a0.y, b0.y);
        e1r[g] = pk(a0.z, b0.z); e1i[g] = pk(a0.w, b0.w);
        e2r[g] = pk(a1.x, b1.x); e2i[g] = pk(a1.y, b1.y);
        e3r[g] = pk(a1.z, b1.z); e3i[g] = pk(a1.w, b1.w);
    }

    // Double-buffered warp-boundary exchange; one __syncthreads per step.
    __shared__ u64 sE0r[2][G][8], sE0i[2][G][8], sE3r[2][G][8], sE3i[2][G][8];

    for (int c = 0; c < NSTEP; c++) {
        const int base = c * 16 * NTH + t;

        // ---- A coefficients (chunks 0..7) ----
        ulonglong2 a0q0 = C[base + 0 * NTH], a0q1 = C[base + 1 * NTH];
        ulonglong2 a0q2 = C[base + 2 * NTH], a0q3 = C[base + 3 * NTH];
        ulonglong2 a1q0 = C[base + 4 * NTH], a1q1 = C[base + 5 * NTH];
        ulonglong2 a1q2 = C[base + 6 * NTH], a1q3 = C[base + 7 * NTH];

        // ---- Rotation A, pair class 0: (e0,e1) ----
#pragma unroll
        for (int g = 0; g < G; g++) {
            u64 ar = mul2(a0q0.x, e0r[g]); ar = fma2(a0q1.x, e0i[g], ar);
            ar = fma2(a0q1.y, e1r[g], ar); ar = fma2(a0q2.y, e1i[g], ar);
            u64 ai = mul2(a0q0.x, e0i[g]); ai = fma2(a0q0.y, e0r[g], ai);
            ai = fma2(a0q1.y, e1i[g], ai); ai = fma2(a0q2.x, e1r[g], ai);
            u64 br = mul2(a0q3.x, e1r[g]); br = fma2(a0q3.y, e0r[g], br);
            u64 bi = mul2(a0q3.x, e1i[g]); bi = fma2(a0q3.y, e0i[g], bi);
            e0r[g] = ar; e0i[g] = ai; e1r[g] = br; e1i[g] = bi;
        }

        // ---- B coefficients (chunks 8..15) issued here to hide L2 latency ----
        ulonglong2 blq0 = C[base + 8 * NTH],  blq1 = C[base + 9 * NTH];
        ulonglong2 blq2 = C[base + 10 * NTH], blq3 = C[base + 11 * NTH];
        ulonglong2 bbq0 = C[base + 12 * NTH], bbq1 = C[base + 13 * NTH];
        ulonglong2 bbq2 = C[base + 14 * NTH], bbq3 = C[base + 15 * NTH];

        // ---- Rotation A, pair class 1: (e2,e3) ----
#pragma unroll
        for (int g = 0; g < G; g++) {
            u64 cr = mul2(a1q0.x, e2r[g]); cr = fma2(a1q1.x, e2i[g], cr);
            cr = fma2(a1q1.y, e3r[g], cr); cr = fma2(a1q2.y, e3i[g], cr);
            u64 ci = mul2(a1q0.x, e2i[g]); ci = fma2(a1q0.y, e2r[g], ci);
            ci = fma2(a1q1.y, e3i[g], ci); ci = fma2(a1q2.x, e3r[g], ci);
            u64 xr = mul2(a1q3.x, e3r[g]); xr = fma2(a1q3.y, e2r[g], xr);
            u64 xi = mul2(a1q3.x, e3i[g]); xi = fma2(a1q3.y, e2i[g], xi);
            e2r[g] = cr; e2i[g] = ci; e3r[g] = xr; e3i[g] = xi;
        }

        // Edge publish (post-rotA values)
        const int buf = c & 1;
        if (lane == 0) {
#pragma unroll
            for (int g = 0; g < G; g++) { sE0r[buf][g][w] = e0r[g]; sE0i[buf][g][w] = e0i[g]; }
        }
        if (lane == 31) {
#pragma unroll
            for (int g = 0; g < G; g++) { sE3r[buf][g][w] = e3r[g]; sE3i[buf][g][w] = e3i[g]; }
        }

        // ---- Rotation B, local pair (e1,e2): no exchange needed, pre-barrier ----
#pragma unroll
        for (int g = 0; g < G; g++) {
            u64 ar = mul2(blq0.x, e1r[g]); ar = fma2(blq1.x, e1i[g], ar);
            ar = fma2(blq1.y, e2r[g], ar); ar = fma2(blq2.y, e2i[g], ar);
            u64 ai = mul2(blq0.x, e1i[g]); ai = fma2(blq0.y, e1r[g], ai);
            ai = fma2(blq1.y, e2i[g], ai); ai = fma2(blq2.x, e2r[g], ai);
            u64 br = mul2(blq3.x, e2r[g]); br = fma2(blq3.y, e1r[g], br);
            u64 bi = mul2(blq3.x, e2i[g]); bi = fma2(blq3.y, e1i[g], bi);
            e1r[g] = ar; e1i[g] = ai; e2r[g] = br; e2i[g] = bi;
        }

        __syncthreads();

        // ---- Rotation B, boundary pair: (e3, next-thread e0) ----
        {
            const int wn = (w + 1) & 7, wp = (w + 7) & 7;
#pragma unroll
            for (int g = 0; g < G; g++) {
                u64 nbr = __shfl_down_sync(0xffffffffu, e0r[g], 1);
                u64 nbi = __shfl_down_sync(0xffffffffu, e0i[g], 1);
                u64 pvr = __shfl_up_sync(0xffffffffu, e3r[g], 1);
                u64 pvi = __shfl_up_sync(0xffffffffu, e3i[g], 1);
                if (lane == 31) { nbr = sE0r[buf][g][wn]; nbi = sE0i[buf][g][wn]; }
                if (lane == 0)  { pvr = sE3r[buf][g][wp]; pvi = sE3i[buf][g][wp]; }

                u64 cr = mul2(bbq0.x, e3r[g]); cr = fma2(bbq1.x, e3i[g], cr);
                cr = fma2(bbq1.y, nbr, cr);    cr = fma2(bbq2.y, nbi, cr);
                u64 ci = mul2(bbq0.x, e3i[g]); ci = fma2(bbq0.y, e3r[g], ci);
                ci = fma2(bbq1.y, nbi, ci);    ci = fma2(bbq2.x, nbr, ci);
                u64 zr = mul2(bbq3.x, e0r[g]); zr = fma2(bbq3.y, pvr, zr);
                u64 zi = mul2(bbq3.x, e0i[g]); zi = fma2(bbq3.y, pvi, zi);
                e3r[g] = cr; e3i[g] = ci; e0r[g] = zr; e0i[g] = zi;
            }
        }
    }

#pragma unroll
    for (int g = 0; g < G; g++) {
        size_t r0 = (size_t)(row0 + 2 * g) * 512;
        size_t r1 = r0 + 512;
        float a, b;
        float4 o0, o1, p0, p1;
        upk(e0r[g], a, b); o0.x = a; p0.x = b;
        upk(e0i[g], a, b); o0.y = a; p0.y = b;
        upk(e1r[g], a, b); o0.z = a; p0.z = b;
        upk(e1i[g], a, b); o0.w = a; p0.w = b;
        upk(e2r[g], a, b); o1.x = a; p1.x = b;
        upk(e2i[g], a, b); o1.y = a; p1.y = b;
        upk(e3r[g], a, b); o1.z = a; p1.z = b;
        upk(e3i[g], a, b); o1.w = a; p1.w = b;
        xout[r0 + 2 * t]     = o0;
        xout[r0 + 2 * t + 1] = o1;
        xout[r1 + 2 * t]     = p0;
        xout[r1 + 2 * t + 1] = p1;
    }
}

extern "C" void kernel_launch(void* const* d_in, const int* in_sizes, int n_in,
                              void* d_out, int out_size) {
    const float* x    = (const float*)d_in[0];
    const float* phi0 = (const float*)d_in[1];
    const float* th0  = (const float*)d_in[2];
    const float* phi1 = (const float*)d_in[3];
    const float* th1  = (const float*)d_in[4];

    coeff_kernel<<<(NSTEP * 512 + 255) / 256, 256>>>(phi0, th0, phi1, th1);
    eunn_kernel<<<4096 / (2 * G), NTH>>>((const float4*)x, (float4*)d_out);
}

// round 5
// speedup vs baseline: 1.4327x; 1.4327x over previous
#include <cuda_runtime.h>

typedef unsigned long long u64;

#define NSTEP 256   // C2
#define NTH   128   // threads per block; thread t owns complex elements 8t..8t+7
#define G     2     // f32x2 row-groups (2 batch rows each) -> 4 rows per block
#define SGN   0x8000000080000000ULL

// Compact coefficient streams: [step][chunk 0..11][thread], 256*12*128*16B = 6.29 MB.
// chunks 0..3:  rotA pairs 4t+0..3 (dr,di,or,oi)
// chunk  4:     (ctA[4t],stA[4t],ctA[4t+1],stA[4t+1])
// chunk  5:     (ctA[4t+2],stA[4t+2],ctA[4t+3],stA[4t+3])
// chunks 6..9:  rotB pairs 4t+0..3 (dr,di,or,oi)   (pair 4t+3 = boundary)
// chunk  10:    (ctB[4t],stB[4t],ctB[4t+1],stB[4t+1])
// chunk  11:    (ctB[4t+2],stB[4t+2],ctB[4t-1],stB[4t-1])  [zw pre-shifted]
__device__ float4 gC[NSTEP * 12 * NTH];

__device__ __forceinline__ u64 pk2(float x) {
    u64 r; asm("mov.b64 %0, {%1, %1};" : "=l"(r) : "f"(x)); return r;
}
__device__ __forceinline__ u64 pk(float lo, float hi) {
    u64 r; asm("mov.b64 %0, {%1, %2};" : "=l"(r) : "f"(lo), "f"(hi)); return r;
}
__device__ __forceinline__ void upk(u64 v, float& lo, float& hi) {
    asm("mov.b64 {%0, %1}, %2;" : "=f"(lo), "=f"(hi) : "l"(v));
}
__device__ __forceinline__ u64 mul2(u64 a, u64 b) {
    u64 r; asm("mul.rn.f32x2 %0, %1, %2;" : "=l"(r) : "l"(a), "l"(b)); return r;
}
__device__ __forceinline__ u64 fma2(u64 a, u64 b, u64 c) {
    u64 r; asm("fma.rn.f32x2 %0, %1, %2, %3;" : "=l"(r) : "l"(a), "l"(b), "l"(c)); return r;
}

// Full local pair rotation: (f,s) -> (d*f + o*s, ct*s + st*f), complex d,o; real ct,st.
__device__ __forceinline__ void rotpair(u64* fr, u64* fi, u64* sr, u64* si,
                                        float4 cc, float ctf, float stf) {
    u64 dr = pk2(cc.x), di = pk2(cc.y), orr = pk2(cc.z), oi = pk2(cc.w);
    u64 nd = di ^ SGN, no = oi ^ SGN, ct = pk2(ctf), st = pk2(stf);
#pragma unroll
    for (int g = 0; g < G; g++) {
        u64 ar = mul2(dr, fr[g]); ar = fma2(nd, fi[g], ar);
        ar = fma2(orr, sr[g], ar); ar = fma2(no, si[g], ar);
        u64 ai = mul2(dr, fi[g]); ai = fma2(di, fr[g], ai);
        ai = fma2(orr, si[g], ai); ai = fma2(oi, sr[g], ai);
        u64 br = mul2(ct, sr[g]); br = fma2(st, fr[g], br);
        u64 bi = mul2(ct, si[g]); bi = fma2(st, fi[g], bi);
        fr[g] = ar; fi[g] = ai; sr[g] = br; si[g] = bi;
    }
}

// phi/theta arrays: (H2=512, C2=256) row-major -> [p*256 + c]
__global__ void coeff_kernel(const float* __restrict__ phi0, const float* __restrict__ th0,
                             const float* __restrict__ phi1, const float* __restrict__ th1) {
    int idx = blockIdx.x * blockDim.x + threadIdx.x;
    if (idx >= NSTEP * 512) return;
    int p = idx & 511;     // pair index
    int c = idx >> 9;      // step
    int t = p >> 2;        // owning eunn-thread (0..127)
    int k = p & 3;         // pair slot within thread
    int base = c * 12 * NTH;
    float* F = (float*)gC;

    float sp, cp, st, ct;
    sincosf(phi0[p * NSTEP + c], &sp, &cp);
    sincosf(th0[p * NSTEP + c], &st, &ct);
    gC[base + k * NTH + t] = make_float4(cp * ct, sp * ct, -cp * st, -sp * st);
    {
        int chunk = 4 + (k >> 1), off = (k & 1) * 2;
        F[(base + chunk * NTH + t) * 4 + off]     = ct;
        F[(base + chunk * NTH + t) * 4 + off + 1] = st;
    }

    sincosf(phi1[p * NSTEP + c], &sp, &cp);
    sincosf(th1[p * NSTEP + c], &st, &ct);
    gC[base + (6 + k) * NTH + t] = make_float4(cp * ct, sp * ct, -cp * st, -sp * st);
    if (k < 2) {
        F[(base + 10 * NTH + t) * 4 + k * 2]     = ct;
        F[(base + 10 * NTH + t) * 4 + k * 2 + 1] = st;
    } else if (k == 2) {
        F[(base + 11 * NTH + t) * 4 + 0] = ct;
        F[(base + 11 * NTH + t) * 4 + 1] = st;
    } else {
        // pair 4t+3's (ct,st) is consumed as "previous pair" by thread t+1 (mod 128)
        int ts = (t + 1) & (NTH - 1);
        F[(base + 11 * NTH + ts) * 4 + 2] = ct;
        F[(base + 11 * NTH + ts) * 4 + 3] = st;
    }
}

__global__ void __launch_bounds__(NTH, 4)
eunn_kernel(const float4* __restrict__ xin, float4* __restrict__ xout) {
    const int t    = threadIdx.x;
    const int lane = t & 31;
    const int w    = t >> 5;               // 4 warps
    const int row0 = blockIdx.x * (2 * G); // 4 batch rows per block

    u64 er[8][G], ei[8][G];
#pragma unroll
    for (int g = 0; g < G; g++) {
        size_t r0 = (size_t)(row0 + 2 * g) * 512;
        size_t r1 = r0 + 512;
#pragma unroll
        for (int j = 0; j < 4; j++) {
            float4 a = xin[r0 + 4 * t + j];
            float4 b = xin[r1 + 4 * t + j];
            er[2 * j][g]     = pk(a.x, b.x); ei[2 * j][g]     = pk(a.y, b.y);
            er[2 * j + 1][g] = pk(a.z, b.z); ei[2 * j + 1][g] = pk(a.w, b.w);
        }
    }

    // Double-buffered warp-boundary exchange; one __syncthreads per step.
    __shared__ u64 sE0r[2][G][4], sE0i[2][G][4], sE7r[2][G][4], sE7i[2][G][4];

    for (int c = 0; c < NSTEP; c++) {
        const int base = c * 12 * NTH + t;
        float4 k0 = gC[base + 0 * NTH], k1 = gC[base + 1 * NTH];
        float4 k2 = gC[base + 2 * NTH], k3 = gC[base + 3 * NTH];
        float4 k4 = gC[base + 4 * NTH], k5 = gC[base + 5 * NTH];

        // ---- Rotation A: pairs (e0,e1), (e2,e3) ----
        rotpair(er[0], ei[0], er[1], ei[1], k0, k4.x, k4.y);
        rotpair(er[2], ei[2], er[3], ei[3], k1, k4.z, k4.w);

        // Issue B coefficient loads here so compute covers their latency
        float4 k6 = gC[base + 6 * NTH], k7 = gC[base + 7 * NTH];
        float4 k8 = gC[base + 8 * NTH], k9 = gC[base + 9 * NTH];
        float4 kA = gC[base + 10 * NTH], kB = gC[base + 11 * NTH];

        // ---- Rotation A: pairs (e4,e5), (e6,e7) ----
        rotpair(er[4], ei[4], er[5], ei[5], k2, k5.x, k5.y);
        rotpair(er[6], ei[6], er[7], ei[7], k3, k5.z, k5.w);

        // Edge publish of post-A e0 / e7
        const int buf = c & 1;
        if (lane == 0) {
#pragma unroll
            for (int g = 0; g < G; g++) { sE0r[buf][g][w] = er[0][g]; sE0i[buf][g][w] = ei[0][g]; }
        }
        if (lane == 31) {
#pragma unroll
            for (int g = 0; g < G; g++) { sE7r[buf][g][w] = er[7][g]; sE7i[buf][g][w] = ei[7][g]; }
        }

        // ---- Rotation B, local pairs (e1,e2), (e3,e4), (e5,e6): pre-barrier ----
        rotpair(er[1], ei[1], er[2], ei[2], k6, kA.x, kA.y);
        rotpair(er[3], ei[3], er[4], ei[4], k7, kA.z, kA.w);
        rotpair(er[5], ei[5], er[6], ei[6], k8, kB.x, kB.y);

        __syncthreads();

        // ---- Rotation B, boundary pair: (e7, next-thread e0) ----
        {
            u64 dr = pk2(k9.x), di = pk2(k9.y), orr = pk2(k9.z), oi = pk2(k9.w);
            u64 nd = di ^ SGN, no = oi ^ SGN, ctm = pk2(kB.z), stm = pk2(kB.w);
            const int wn = (w + 1) & 3, wp = (w + 3) & 3;
#pragma unroll
            for (int g = 0; g < G; g++) {
                u64 nbr = __shfl_down_sync(0xffffffffu, er[0][g], 1);
                u64 nbi = __shfl_down_sync(0xffffffffu, ei[0][g], 1);
                u64 pvr = __shfl_up_sync(0xffffffffu, er[7][g], 1);
                u64 pvi = __shfl_up_sync(0xffffffffu, ei[7][g], 1);
                if (lane == 31) { nbr = sE0r[buf][g][wn]; nbi = sE0i[buf][g][wn]; }
                if (lane == 0)  { pvr = sE7r[buf][g][wp]; pvi = sE7i[buf][g][wp]; }

                u64 cr = mul2(dr, er[7][g]); cr = fma2(nd, ei[7][g], cr);
                cr = fma2(orr, nbr, cr);     cr = fma2(no, nbi, cr);
                u64 ci = mul2(dr, ei[7][g]); ci = fma2(di, er[7][g], ci);
                ci = fma2(orr, nbi, ci);     ci = fma2(oi, nbr, ci);
                u64 zr = mul2(ctm, er[0][g]); zr = fma2(stm, pvr, zr);
                u64 zi = mul2(ctm, ei[0][g]); zi = fma2(stm, pvi, zi);
                er[7][g] = cr; ei[7][g] = ci; er[0][g] = zr; ei[0][g] = zi;
            }
        }
    }

#pragma unroll
    for (int g = 0; g < G; g++) {
        size_t r0 = (size_t)(row0 + 2 * g) * 512;
        size_t r1 = r0 + 512;
#pragma unroll
        for (int j = 0; j < 4; j++) {
            float4 a, b;
            upk(er[2 * j][g], a.x, b.x);     upk(ei[2 * j][g], a.y, b.y);
            upk(er[2 * j + 1][g], a.z, b.z); upk(ei[2 * j + 1][g], a.w, b.w);
            xout[r0 + 4 * t + j] = a;
            xout[r1 + 4 * t + j] = b;
        }
    }
}

extern "C" void kernel_launch(void* const* d_in, const int* in_sizes, int n_in,
                              void* d_out, int out_size) {
    const float* x    = (const float*)d_in[0];
    const float* phi0 = (const float*)d_in[1];
    const float* th0  = (const float*)d_in[2];
    const float* phi1 = (const float*)d_in[3];
    const float* th1  = (const float*)d_in[4];

    coeff_kernel<<<(NSTEP * 512 + 255) / 256, 256>>>(phi0, th0, phi1, th1);
    eunn_kernel<<<4096 / (2 * G), NTH>>>((const float4*)x, (float4*)d_out);
}